// round 6
// baseline (speedup 1.0000x reference)
#include <cuda_runtime.h>
#include <cuda_bf16.h>
#include <mma.h>
#include <cstdint>

using namespace nvcuda;

// ---------------- problem constants ----------------
#define HW     4096      // 64*64
#define IMGW   64
#define BATCH  16
#define CIN    256
#define C3     768
#define CCAT   512
#define COUT   256
#define NHEAD  64
#define ATT_EPS 1e-5f

// ---------------- scratch (device globals; no allocations) ----------------
__device__ float g_qkv [(size_t)BATCH * C3   * HW];
__device__ float g_agg [(size_t)BATCH * C3   * HW];
__device__ float g_vk  [BATCH * NHEAD * 72];

// bf16 hi/lo operand mirrors (error-compensated GEMM inputs)
__device__ __nv_bfloat16 g_x_hi   [(size_t)BATCH * CIN  * HW];
__device__ __nv_bfloat16 g_x_lo   [(size_t)BATCH * CIN  * HW];
__device__ __nv_bfloat16 g_attn_hi[(size_t)BATCH * CCAT * HW];
__device__ __nv_bfloat16 g_attn_lo[(size_t)BATCH * CCAT * HW];
__device__ __nv_bfloat16 g_wqkv_hi[C3 * CIN];
__device__ __nv_bfloat16 g_wqkv_lo[C3 * CIN];
__device__ __nv_bfloat16 g_wproj_hi[COUT * CCAT];
__device__ __nv_bfloat16 g_wproj_lo[COUT * CCAT];

// ==========================================================================
// fp32 -> bf16 hi/lo conversion (one pass, float4 granularity)
// ==========================================================================
__global__ __launch_bounds__(256)
void to_hilo_kernel(const float4* __restrict__ src,
                    uint2* __restrict__ hi, uint2* __restrict__ lo, int n4)
{
    int i = blockIdx.x * 256 + threadIdx.x;
    if (i >= n4) return;
    float4 v = src[i];
    float xs[4] = {v.x, v.y, v.z, v.w};
    union { __nv_bfloat16 h[4]; uint2 u; } ph, pl;
    #pragma unroll
    for (int j = 0; j < 4; j++) {
        __nv_bfloat16 hh = __float2bfloat16_rn(xs[j]);
        ph.h[j] = hh;
        pl.h[j] = __float2bfloat16_rn(xs[j] - __bfloat162float(hh));
    }
    hi[i] = ph.u;
    lo[i] = pl.u;
}

// ==========================================================================
// bf16x3 wmma GEMM + BN + ReLU, pre-split operands, register double-buffer.
//   Out[b,m,n] = relu(scale[m] * sum_k W[m,k] X[b,k,n] + bias[m])
// Block 128Mx128N, BK=32, 256 threads (8 warps, warp tile 64x32, 4x2 frags).
// ==========================================================================
#define LDA 40    // bf16 stride (80B row, 16B multiple)
#define LDB 136   // bf16 stride (272B row, 16B multiple)
#define LDC 132   // fp32 epilogue stride

#define OFF_AHI 0
#define OFF_ALO 10240
#define OFF_BHI 20480
#define OFF_BLO 29184
#define SMEM_BYTES 37888   // >= 64*132*4 = 33792 epilogue reuse

template<int Mt, int Kt>
__global__ __launch_bounds__(256)
void gemm_bf16x3(const __nv_bfloat16* __restrict__ Wh,
                 const __nv_bfloat16* __restrict__ Wl,
                 const __nv_bfloat16* __restrict__ Xh,
                 const __nv_bfloat16* __restrict__ Xl,
                 const float* __restrict__ scale,
                 const float* __restrict__ bias,
                 float* __restrict__ Out)
{
    __shared__ __align__(16) char smem[SMEM_BYTES];
    __nv_bfloat16* Ahi = reinterpret_cast<__nv_bfloat16*>(smem + OFF_AHI);
    __nv_bfloat16* Alo = reinterpret_cast<__nv_bfloat16*>(smem + OFF_ALO);
    __nv_bfloat16* Bhi = reinterpret_cast<__nv_bfloat16*>(smem + OFF_BHI);
    __nv_bfloat16* Blo = reinterpret_cast<__nv_bfloat16*>(smem + OFF_BLO);
    float* Cs = reinterpret_cast<float*>(smem);

    const int b     = blockIdx.z;
    const int mBase = blockIdx.y * 128;
    const int nBase = blockIdx.x * 128;
    const int tid   = threadIdx.x;
    const int wid   = tid >> 5;
    const int warpM = wid & 1;
    const int warpN = wid >> 1;

    const __nv_bfloat16* __restrict__ Xhb = Xh + (size_t)b * Kt * HW;
    const __nv_bfloat16* __restrict__ Xlb = Xl + (size_t)b * Kt * HW;

    // A-tile reg indices: 512 uint4 (128 rows x 4), 2 per thread
    const int aRow0 = (tid)       >> 2, aC0 = ((tid)       & 3) * 8;
    const int aRow1 = (tid + 256) >> 2, aC1 = ((tid + 256) & 3) * 8;
    // B-tile: 512 uint4 (32 rows x 16), 2 per thread
    const int bRow0 = (tid)       >> 4, bC0 = ((tid)       & 15) * 8;
    const int bRow1 = (tid + 256) >> 4, bC1 = ((tid + 256) & 15) * 8;

    uint4 rAh[2], rAl[2], rBh[2], rBl[2];

    auto load_regs = [&](int k0) {
        rAh[0] = *reinterpret_cast<const uint4*>(&Wh[(size_t)(mBase + aRow0) * Kt + k0 + aC0]);
        rAh[1] = *reinterpret_cast<const uint4*>(&Wh[(size_t)(mBase + aRow1) * Kt + k0 + aC1]);
        rAl[0] = *reinterpret_cast<const uint4*>(&Wl[(size_t)(mBase + aRow0) * Kt + k0 + aC0]);
        rAl[1] = *reinterpret_cast<const uint4*>(&Wl[(size_t)(mBase + aRow1) * Kt + k0 + aC1]);
        rBh[0] = *reinterpret_cast<const uint4*>(&Xhb[(size_t)(k0 + bRow0) * HW + nBase + bC0]);
        rBh[1] = *reinterpret_cast<const uint4*>(&Xhb[(size_t)(k0 + bRow1) * HW + nBase + bC1]);
        rBl[0] = *reinterpret_cast<const uint4*>(&Xlb[(size_t)(k0 + bRow0) * HW + nBase + bC0]);
        rBl[1] = *reinterpret_cast<const uint4*>(&Xlb[(size_t)(k0 + bRow1) * HW + nBase + bC1]);
    };
    auto store_smem = [&]() {
        *reinterpret_cast<uint4*>(&Ahi[aRow0 * LDA + aC0]) = rAh[0];
        *reinterpret_cast<uint4*>(&Ahi[aRow1 * LDA + aC1]) = rAh[1];
        *reinterpret_cast<uint4*>(&Alo[aRow0 * LDA + aC0]) = rAl[0];
        *reinterpret_cast<uint4*>(&Alo[aRow1 * LDA + aC1]) = rAl[1];
        *reinterpret_cast<uint4*>(&Bhi[bRow0 * LDB + bC0]) = rBh[0];
        *reinterpret_cast<uint4*>(&Bhi[bRow1 * LDB + bC1]) = rBh[1];
        *reinterpret_cast<uint4*>(&Blo[bRow0 * LDB + bC0]) = rBl[0];
        *reinterpret_cast<uint4*>(&Blo[bRow1 * LDB + bC1]) = rBl[1];
    };

    wmma::fragment<wmma::accumulator, 16, 16, 16, float> acc[4][2];
    #pragma unroll
    for (int i = 0; i < 4; i++)
        #pragma unroll
        for (int j = 0; j < 2; j++) wmma::fill_fragment(acc[i][j], 0.f);

    load_regs(0);
    constexpr int NCHUNK = Kt / 32;
    #pragma unroll 1
    for (int chunk = 0; chunk < NCHUNK; chunk++) {
        store_smem();
        __syncthreads();
        if (chunk + 1 < NCHUNK) load_regs((chunk + 1) * 32);

        #pragma unroll
        for (int kk = 0; kk < 2; kk++) {
            wmma::fragment<wmma::matrix_a, 16, 16, 16, __nv_bfloat16,
                           wmma::row_major> afh[4], afl[4];
            wmma::fragment<wmma::matrix_b, 16, 16, 16, __nv_bfloat16,
                           wmma::row_major> bfh[2], bfl[2];
            #pragma unroll
            for (int i = 0; i < 4; i++) {
                const int ro = (warpM * 64 + i * 16) * LDA + kk * 16;
                wmma::load_matrix_sync(afh[i], &Ahi[ro], LDA);
                wmma::load_matrix_sync(afl[i], &Alo[ro], LDA);
            }
            #pragma unroll
            for (int j = 0; j < 2; j++) {
                const int ro = (kk * 16) * LDB + warpN * 32 + j * 16;
                wmma::load_matrix_sync(bfh[j], &Bhi[ro], LDB);
                wmma::load_matrix_sync(bfl[j], &Blo[ro], LDB);
            }
            #pragma unroll
            for (int i = 0; i < 4; i++)
                #pragma unroll
                for (int j = 0; j < 2; j++) {
                    wmma::mma_sync(acc[i][j], afl[i], bfh[j], acc[i][j]);
                    wmma::mma_sync(acc[i][j], afh[i], bfl[j], acc[i][j]);
                    wmma::mma_sync(acc[i][j], afh[i], bfh[j], acc[i][j]);
                }
        }
        __syncthreads();
    }

    // epilogue: two 64-row passes via smem, fused BN + ReLU
    #pragma unroll
    for (int p = 0; p < 2; p++) {
        if (warpM == p) {
            #pragma unroll
            for (int i = 0; i < 4; i++)
                #pragma unroll
                for (int j = 0; j < 2; j++)
                    wmma::store_matrix_sync(
                        &Cs[(i * 16) * LDC + warpN * 32 + j * 16],
                        acc[i][j], LDC, wmma::mem_row_major);
        }
        __syncthreads();
        #pragma unroll
        for (int t = 0; t < 8; t++) {
            int idx = tid + t * 256;
            int r = idx >> 5, c4 = (idx & 31) * 4;
            int m = mBase + p * 64 + r;
            const float sc = scale[m], bi = bias[m];
            float4 v = *reinterpret_cast<const float4*>(&Cs[r * LDC + c4]);
            v.x = fmaxf(fmaf(v.x, sc, bi), 0.f);
            v.y = fmaxf(fmaf(v.y, sc, bi), 0.f);
            v.z = fmaxf(fmaf(v.z, sc, bi), 0.f);
            v.w = fmaxf(fmaf(v.w, sc, bi), 0.f);
            *reinterpret_cast<float4*>(
                &Out[(size_t)b * Mt * HW + (size_t)m * HW + nBase + c4]) = v;
        }
        __syncthreads();
    }
}

// ==========================================================================
// Fused depthwise 5x5 (pad 2, +bias) then per-channel 1x1 (*w, +bias).
// ==========================================================================
__global__ __launch_bounds__(256)
void dw5x5_pw_kernel(const float* __restrict__ dw_w,
                     const float* __restrict__ dw_b,
                     const float* __restrict__ pw_w,
                     const float* __restrict__ pw_b)
{
    const int c = blockIdx.y;
    const int b = blockIdx.z;
    const int p = blockIdx.x * 256 + threadIdx.x;
    const int y = p >> 6;
    const int x = p & 63;

    const float* __restrict__ src = g_qkv + ((size_t)b * C3 + c) * HW;

    float wreg[25];
    #pragma unroll
    for (int i = 0; i < 25; i++) wreg[i] = __ldg(&dw_w[c * 25 + i]);

    float s = 0.f;
    #pragma unroll
    for (int dy = 0; dy < 5; dy++) {
        const int yy = y + dy - 2;
        if (yy < 0 || yy >= IMGW) continue;
        const float* row = src + yy * IMGW;
        #pragma unroll
        for (int dx = 0; dx < 5; dx++) {
            const int xx = x + dx - 2;
            if (xx < 0 || xx >= IMGW) continue;
            s = fmaf(__ldg(&row[xx]), wreg[dy * 5 + dx], s);
        }
    }
    s = fmaf(s + __ldg(&dw_b[c]), __ldg(&pw_w[c]), __ldg(&pw_b[c]));
    g_agg[((size_t)b * C3 + c) * HW + p] = s;
}

// ==========================================================================
// Attention phase 1: per (b, head): vk[d][e] = sum_n v*relu(k); ksum[e]
// ==========================================================================
__global__ __launch_bounds__(256)
void attn_reduce_kernel()
{
    const int head = blockIdx.x;
    const int b    = blockIdx.y;
    const float* __restrict__ src = (head < 32) ? g_qkv : g_agg;
    const int ch0 = (head & 31) * 24;
    const float* __restrict__ base = src + ((size_t)b * C3 + ch0) * HW;

    float acc[72];
    #pragma unroll
    for (int i = 0; i < 72; i++) acc[i] = 0.f;

    for (int n = threadIdx.x; n < HW; n += 256) {
        float kv[8], vv[8];
        #pragma unroll
        for (int e = 0; e < 8; e++) kv[e] = fmaxf(base[(size_t)(8 + e) * HW + n], 0.f);
        #pragma unroll
        for (int d = 0; d < 8; d++) vv[d] = base[(size_t)(16 + d) * HW + n];
        #pragma unroll
        for (int d = 0; d < 8; d++)
            #pragma unroll
            for (int e = 0; e < 8; e++)
                acc[d * 8 + e] = fmaf(vv[d], kv[e], acc[d * 8 + e]);
        #pragma unroll
        for (int e = 0; e < 8; e++) acc[64 + e] += kv[e];
    }

    __shared__ float s_acc[72];
    if (threadIdx.x < 72) s_acc[threadIdx.x] = 0.f;
    __syncthreads();

    const int lane = threadIdx.x & 31;
    #pragma unroll
    for (int i = 0; i < 72; i++) {
        float v = acc[i];
        #pragma unroll
        for (int off = 16; off > 0; off >>= 1)
            v += __shfl_down_sync(0xffffffffu, v, off);
        if (lane == 0) atomicAdd(&s_acc[i], v);
    }
    __syncthreads();
    if (threadIdx.x < 72)
        g_vk[((size_t)b * NHEAD + head) * 72 + threadIdx.x] = s_acc[threadIdx.x];
}

// ==========================================================================
// Attention phase 2: apply + normalize; emits bf16 hi/lo for the proj GEMM
// ==========================================================================
__global__ __launch_bounds__(256)
void attn_apply_kernel()
{
    const int head = blockIdx.y;
    const int b    = blockIdx.z;
    const int n    = blockIdx.x * 256 + threadIdx.x;

    __shared__ float s[72];
    if (threadIdx.x < 72)
        s[threadIdx.x] = g_vk[((size_t)b * NHEAD + head) * 72 + threadIdx.x];
    __syncthreads();

    const float* __restrict__ src = (head < 32) ? g_qkv : g_agg;
    const int ch0 = (head & 31) * 24;
    const float* __restrict__ base = src + ((size_t)b * C3 + ch0) * HW;

    float q[8];
    #pragma unroll
    for (int e = 0; e < 8; e++) q[e] = fmaxf(base[(size_t)e * HW + n], 0.f);

    float denom = ATT_EPS;
    #pragma unroll
    for (int e = 0; e < 8; e++) denom = fmaf(s[64 + e], q[e], denom);
    const float inv = 1.f / denom;

    const size_t obase = ((size_t)b * CCAT + head * 8) * HW + n;
    #pragma unroll
    for (int d = 0; d < 8; d++) {
        float o = 0.f;
        #pragma unroll
        for (int e = 0; e < 8; e++) o = fmaf(s[d * 8 + e], q[e], o);
        float val = o * inv;
        __nv_bfloat16 hh = __float2bfloat16_rn(val);
        g_attn_hi[obase + (size_t)d * HW] = hh;
        g_attn_lo[obase + (size_t)d * HW] =
            __float2bfloat16_rn(val - __bfloat162float(hh));
    }
}

// ==========================================================================
// launcher
// ==========================================================================
extern "C" void kernel_launch(void* const* d_in, const int* in_sizes, int n_in,
                              void* d_out, int out_size)
{
    const float* x            = (const float*)d_in[0];
    const float* qkv_w        = (const float*)d_in[1];
    const float* qkv_bn_scale = (const float*)d_in[2];
    const float* qkv_bn_bias  = (const float*)d_in[3];
    const float* agg_dw_w     = (const float*)d_in[4];
    const float* agg_dw_b     = (const float*)d_in[5];
    const float* agg_pw_w     = (const float*)d_in[6];
    const float* agg_pw_b     = (const float*)d_in[7];
    const float* proj_w       = (const float*)d_in[8];
    const float* proj_bn_scale= (const float*)d_in[9];
    const float* proj_bn_bias = (const float*)d_in[10];
    float* out = (float*)d_out;

    __nv_bfloat16 *xh, *xl, *wqh, *wql, *wph, *wpl, *ah, *al;
    cudaGetSymbolAddress((void**)&xh,  g_x_hi);
    cudaGetSymbolAddress((void**)&xl,  g_x_lo);
    cudaGetSymbolAddress((void**)&wqh, g_wqkv_hi);
    cudaGetSymbolAddress((void**)&wql, g_wqkv_lo);
    cudaGetSymbolAddress((void**)&wph, g_wproj_hi);
    cudaGetSymbolAddress((void**)&wpl, g_wproj_lo);
    cudaGetSymbolAddress((void**)&ah,  g_attn_hi);
    cudaGetSymbolAddress((void**)&al,  g_attn_lo);

    // 0) pre-split operands to bf16 hi/lo
    {
        int n4 = (BATCH * CIN * HW) / 4;
        to_hilo_kernel<<<(n4 + 255) / 256, 256>>>(
            (const float4*)x, (uint2*)xh, (uint2*)xl, n4);
        int w4 = (C3 * CIN) / 4;
        to_hilo_kernel<<<(w4 + 255) / 256, 256>>>(
            (const float4*)qkv_w, (uint2*)wqh, (uint2*)wql, w4);
        int p4 = (COUT * CCAT) / 4;
        to_hilo_kernel<<<(p4 + 255) / 256, 256>>>(
            (const float4*)proj_w, (uint2*)wph, (uint2*)wpl, p4);
    }
    // 1) qkv = relu(bn(conv1x1(x)))
    {
        float* gq;
        cudaGetSymbolAddress((void**)&gq, g_qkv);
        dim3 grid(HW / 128, C3 / 128, BATCH);
        gemm_bf16x3<C3, CIN><<<grid, 256>>>(
            wqh, wql, xh, xl, qkv_bn_scale, qkv_bn_bias, gq);
    }
    // 2) agg = pw(dw5x5(qkv))
    {
        dim3 grid(HW / 256, C3, BATCH);
        dw5x5_pw_kernel<<<grid, 256>>>(agg_dw_w, agg_dw_b, agg_pw_w, agg_pw_b);
    }
    // 3a) per-head vk / ksum
    {
        dim3 grid(NHEAD, BATCH);
        attn_reduce_kernel<<<grid, 256>>>();
    }
    // 3b) apply + normalize (emits bf16 hi/lo)
    {
        dim3 grid(HW / 256, NHEAD, BATCH);
        attn_apply_kernel<<<grid, 256>>>();
    }
    // 4) out = relu(bn(conv1x1(attn)))
    {
        dim3 grid(HW / 128, COUT / 128, BATCH);
        gemm_bf16x3<COUT, CCAT><<<grid, 256>>>(
            wph, wpl, ah, al, proj_bn_scale, proj_bn_bias, out);
    }
}

// round 7
// speedup vs baseline: 1.1448x; 1.1448x over previous
#include <cuda_runtime.h>
#include <cuda_bf16.h>
#include <mma.h>
#include <cstdint>

using namespace nvcuda;

// ---------------- problem constants ----------------
#define HW     4096      // 64*64
#define IMGW   64
#define BATCH  16
#define CIN    256
#define C3     768
#define CCAT   512
#define COUT   256
#define NHEAD  64
#define ATT_EPS 1e-5f

// ---------------- scratch (device globals; no allocations) ----------------
__device__ float g_qkv [(size_t)BATCH * C3   * HW];
__device__ float g_agg [(size_t)BATCH * C3   * HW];
__device__ float g_vk  [BATCH * NHEAD * 72];

// bf16 hi/lo operand mirrors (error-compensated GEMM inputs)
__device__ __nv_bfloat16 g_x_hi   [(size_t)BATCH * CIN  * HW];
__device__ __nv_bfloat16 g_x_lo   [(size_t)BATCH * CIN  * HW];
__device__ __nv_bfloat16 g_attn_hi[(size_t)BATCH * CCAT * HW];
__device__ __nv_bfloat16 g_attn_lo[(size_t)BATCH * CCAT * HW];
__device__ __nv_bfloat16 g_wqkv_hi[C3 * CIN];
__device__ __nv_bfloat16 g_wqkv_lo[C3 * CIN];
__device__ __nv_bfloat16 g_wproj_hi[COUT * CCAT];
__device__ __nv_bfloat16 g_wproj_lo[COUT * CCAT];

// ==========================================================================
// fp32 -> bf16 hi/lo conversion (one pass, float4 granularity)
// ==========================================================================
__global__ __launch_bounds__(256)
void to_hilo_kernel(const float4* __restrict__ src,
                    uint2* __restrict__ hi, uint2* __restrict__ lo, int n4)
{
    int i = blockIdx.x * 256 + threadIdx.x;
    if (i >= n4) return;
    float4 v = src[i];
    float xs[4] = {v.x, v.y, v.z, v.w};
    union { __nv_bfloat16 h[4]; uint2 u; } ph, pl;
    #pragma unroll
    for (int j = 0; j < 4; j++) {
        __nv_bfloat16 hh = __float2bfloat16_rn(xs[j]);
        ph.h[j] = hh;
        pl.h[j] = __float2bfloat16_rn(xs[j] - __bfloat162float(hh));
    }
    hi[i] = ph.u;
    lo[i] = pl.u;
}

// ==========================================================================
// bf16x3 wmma GEMM + BN + ReLU, pre-split operands, 2 CTAs/SM.
//   Out[b,m,n] = relu(scale[m] * sum_k W[m,k] X[b,k,n] + bias[m])
// Block 128Mx128N, BK=32, 256 threads (8 warps, warp tile 64x32, 4x2 frags).
// Low register pressure: B frags loaded once per k-step, A frags streamed.
// ==========================================================================
#define LDA 40    // bf16 stride (80B row)
#define LDB 136   // bf16 stride (272B row)
#define LDC 132   // fp32 epilogue stride

#define OFF_AHI 0
#define OFF_ALO 10240
#define OFF_BHI 20480
#define OFF_BLO 29184
#define SMEM_BYTES 37888   // >= 64*132*4 = 33792 epilogue reuse

template<int Mt, int Kt>
__global__ __launch_bounds__(256, 2)
void gemm_bf16x3(const __nv_bfloat16* __restrict__ Wh,
                 const __nv_bfloat16* __restrict__ Wl,
                 const __nv_bfloat16* __restrict__ Xh,
                 const __nv_bfloat16* __restrict__ Xl,
                 const float* __restrict__ scale,
                 const float* __restrict__ bias,
                 float* __restrict__ Out)
{
    __shared__ __align__(16) char smem[SMEM_BYTES];
    __nv_bfloat16* Ahi = reinterpret_cast<__nv_bfloat16*>(smem + OFF_AHI);
    __nv_bfloat16* Alo = reinterpret_cast<__nv_bfloat16*>(smem + OFF_ALO);
    __nv_bfloat16* Bhi = reinterpret_cast<__nv_bfloat16*>(smem + OFF_BHI);
    __nv_bfloat16* Blo = reinterpret_cast<__nv_bfloat16*>(smem + OFF_BLO);
    float* Cs = reinterpret_cast<float*>(smem);

    const int b     = blockIdx.z;
    const int mBase = blockIdx.y * 128;
    const int nBase = blockIdx.x * 128;
    const int tid   = threadIdx.x;
    const int wid   = tid >> 5;
    const int warpM = wid & 1;
    const int warpN = wid >> 1;

    const __nv_bfloat16* __restrict__ Xhb = Xh + (size_t)b * Kt * HW;
    const __nv_bfloat16* __restrict__ Xlb = Xl + (size_t)b * Kt * HW;

    // A staging: 512 uint4 (128 rows x 4 per row), 2 per thread
    const int aRow0 = (tid)       >> 2, aC0 = ((tid)       & 3) * 8;
    const int aRow1 = (tid + 256) >> 2, aC1 = ((tid + 256) & 3) * 8;
    // B staging: 512 uint4 (32 rows x 16 per row), 2 per thread
    const int bRow0 = (tid)       >> 4, bC0 = ((tid)       & 15) * 8;
    const int bRow1 = (tid + 256) >> 4, bC1 = ((tid + 256) & 15) * 8;

    wmma::fragment<wmma::accumulator, 16, 16, 16, float> acc[4][2];
    #pragma unroll
    for (int i = 0; i < 4; i++)
        #pragma unroll
        for (int j = 0; j < 2; j++) wmma::fill_fragment(acc[i][j], 0.f);

    constexpr int NCHUNK = Kt / 32;
    #pragma unroll 1
    for (int chunk = 0; chunk < NCHUNK; chunk++) {
        const int k0 = chunk * 32;
        // ---- stage A/B tiles (pure bf16 copies)
        *reinterpret_cast<uint4*>(&Ahi[aRow0 * LDA + aC0]) =
            *reinterpret_cast<const uint4*>(&Wh[(size_t)(mBase + aRow0) * Kt + k0 + aC0]);
        *reinterpret_cast<uint4*>(&Ahi[aRow1 * LDA + aC1]) =
            *reinterpret_cast<const uint4*>(&Wh[(size_t)(mBase + aRow1) * Kt + k0 + aC1]);
        *reinterpret_cast<uint4*>(&Alo[aRow0 * LDA + aC0]) =
            *reinterpret_cast<const uint4*>(&Wl[(size_t)(mBase + aRow0) * Kt + k0 + aC0]);
        *reinterpret_cast<uint4*>(&Alo[aRow1 * LDA + aC1]) =
            *reinterpret_cast<const uint4*>(&Wl[(size_t)(mBase + aRow1) * Kt + k0 + aC1]);
        *reinterpret_cast<uint4*>(&Bhi[bRow0 * LDB + bC0]) =
            *reinterpret_cast<const uint4*>(&Xhb[(size_t)(k0 + bRow0) * HW + nBase + bC0]);
        *reinterpret_cast<uint4*>(&Bhi[bRow1 * LDB + bC1]) =
            *reinterpret_cast<const uint4*>(&Xhb[(size_t)(k0 + bRow1) * HW + nBase + bC1]);
        *reinterpret_cast<uint4*>(&Blo[bRow0 * LDB + bC0]) =
            *reinterpret_cast<const uint4*>(&Xlb[(size_t)(k0 + bRow0) * HW + nBase + bC0]);
        *reinterpret_cast<uint4*>(&Blo[bRow1 * LDB + bC1]) =
            *reinterpret_cast<const uint4*>(&Xlb[(size_t)(k0 + bRow1) * HW + nBase + bC1]);
        __syncthreads();

        #pragma unroll
        for (int kk = 0; kk < 2; kk++) {
            wmma::fragment<wmma::matrix_b, 16, 16, 16, __nv_bfloat16,
                           wmma::row_major> bfh[2], bfl[2];
            #pragma unroll
            for (int j = 0; j < 2; j++) {
                const int ro = (kk * 16) * LDB + warpN * 32 + j * 16;
                wmma::load_matrix_sync(bfh[j], &Bhi[ro], LDB);
                wmma::load_matrix_sync(bfl[j], &Blo[ro], LDB);
            }
            #pragma unroll
            for (int i = 0; i < 4; i++) {
                wmma::fragment<wmma::matrix_a, 16, 16, 16, __nv_bfloat16,
                               wmma::row_major> afh, afl;
                const int ro = (warpM * 64 + i * 16) * LDA + kk * 16;
                wmma::load_matrix_sync(afh, &Ahi[ro], LDA);
                wmma::load_matrix_sync(afl, &Alo[ro], LDA);
                #pragma unroll
                for (int j = 0; j < 2; j++) {
                    wmma::mma_sync(acc[i][j], afl, bfh[j], acc[i][j]);
                    wmma::mma_sync(acc[i][j], afh, bfl[j], acc[i][j]);
                    wmma::mma_sync(acc[i][j], afh, bfh[j], acc[i][j]);
                }
            }
        }
        __syncthreads();
    }

    // ---- epilogue: two 64-row passes via smem, fused BN + ReLU
    #pragma unroll
    for (int p = 0; p < 2; p++) {
        if (warpM == p) {
            #pragma unroll
            for (int i = 0; i < 4; i++)
                #pragma unroll
                for (int j = 0; j < 2; j++)
                    wmma::store_matrix_sync(
                        &Cs[(i * 16) * LDC + warpN * 32 + j * 16],
                        acc[i][j], LDC, wmma::mem_row_major);
        }
        __syncthreads();
        #pragma unroll
        for (int t = 0; t < 8; t++) {
            int idx = tid + t * 256;
            int r = idx >> 5, c4 = (idx & 31) * 4;
            int m = mBase + p * 64 + r;
            const float sc = scale[m], bi = bias[m];
            float4 v = *reinterpret_cast<const float4*>(&Cs[r * LDC + c4]);
            v.x = fmaxf(fmaf(v.x, sc, bi), 0.f);
            v.y = fmaxf(fmaf(v.y, sc, bi), 0.f);
            v.z = fmaxf(fmaf(v.z, sc, bi), 0.f);
            v.w = fmaxf(fmaf(v.w, sc, bi), 0.f);
            *reinterpret_cast<float4*>(
                &Out[(size_t)b * Mt * HW + (size_t)m * HW + nBase + c4]) = v;
        }
        __syncthreads();
    }
}

// ==========================================================================
// Fused depthwise 5x5 (pad 2, +bias) then per-channel 1x1 (*w, +bias).
// ==========================================================================
__global__ __launch_bounds__(256)
void dw5x5_pw_kernel(const float* __restrict__ dw_w,
                     const float* __restrict__ dw_b,
                     const float* __restrict__ pw_w,
                     const float* __restrict__ pw_b)
{
    const int c = blockIdx.y;
    const int b = blockIdx.z;
    const int p = blockIdx.x * 256 + threadIdx.x;
    const int y = p >> 6;
    const int x = p & 63;

    const float* __restrict__ src = g_qkv + ((size_t)b * C3 + c) * HW;

    float wreg[25];
    #pragma unroll
    for (int i = 0; i < 25; i++) wreg[i] = __ldg(&dw_w[c * 25 + i]);

    float s = 0.f;
    #pragma unroll
    for (int dy = 0; dy < 5; dy++) {
        const int yy = y + dy - 2;
        if (yy < 0 || yy >= IMGW) continue;
        const float* row = src + yy * IMGW;
        #pragma unroll
        for (int dx = 0; dx < 5; dx++) {
            const int xx = x + dx - 2;
            if (xx < 0 || xx >= IMGW) continue;
            s = fmaf(__ldg(&row[xx]), wreg[dy * 5 + dx], s);
        }
    }
    s = fmaf(s + __ldg(&dw_b[c]), __ldg(&pw_w[c]), __ldg(&pw_b[c]));
    g_agg[((size_t)b * C3 + c) * HW + p] = s;
}

// ==========================================================================
// Attention phase 1: per (b, head): vk[d][e] = sum_n v*relu(k); ksum[e]
// ==========================================================================
__global__ __launch_bounds__(256)
void attn_reduce_kernel()
{
    const int head = blockIdx.x;
    const int b    = blockIdx.y;
    const float* __restrict__ src = (head < 32) ? g_qkv : g_agg;
    const int ch0 = (head & 31) * 24;
    const float* __restrict__ base = src + ((size_t)b * C3 + ch0) * HW;

    float acc[72];
    #pragma unroll
    for (int i = 0; i < 72; i++) acc[i] = 0.f;

    for (int n = threadIdx.x; n < HW; n += 256) {
        float kv[8], vv[8];
        #pragma unroll
        for (int e = 0; e < 8; e++) kv[e] = fmaxf(base[(size_t)(8 + e) * HW + n], 0.f);
        #pragma unroll
        for (int d = 0; d < 8; d++) vv[d] = base[(size_t)(16 + d) * HW + n];
        #pragma unroll
        for (int d = 0; d < 8; d++)
            #pragma unroll
            for (int e = 0; e < 8; e++)
                acc[d * 8 + e] = fmaf(vv[d], kv[e], acc[d * 8 + e]);
        #pragma unroll
        for (int e = 0; e < 8; e++) acc[64 + e] += kv[e];
    }

    __shared__ float s_acc[72];
    if (threadIdx.x < 72) s_acc[threadIdx.x] = 0.f;
    __syncthreads();

    const int lane = threadIdx.x & 31;
    #pragma unroll
    for (int i = 0; i < 72; i++) {
        float v = acc[i];
        #pragma unroll
        for (int off = 16; off > 0; off >>= 1)
            v += __shfl_down_sync(0xffffffffu, v, off);
        if (lane == 0) atomicAdd(&s_acc[i], v);
    }
    __syncthreads();
    if (threadIdx.x < 72)
        g_vk[((size_t)b * NHEAD + head) * 72 + threadIdx.x] = s_acc[threadIdx.x];
}

// ==========================================================================
// Attention phase 2: apply + normalize; emits bf16 hi/lo for the proj GEMM
// ==========================================================================
__global__ __launch_bounds__(256)
void attn_apply_kernel()
{
    const int head = blockIdx.y;
    const int b    = blockIdx.z;
    const int n    = blockIdx.x * 256 + threadIdx.x;

    __shared__ float s[72];
    if (threadIdx.x < 72)
        s[threadIdx.x] = g_vk[((size_t)b * NHEAD + head) * 72 + threadIdx.x];
    __syncthreads();

    const float* __restrict__ src = (head < 32) ? g_qkv : g_agg;
    const int ch0 = (head & 31) * 24;
    const float* __restrict__ base = src + ((size_t)b * C3 + ch0) * HW;

    float q[8];
    #pragma unroll
    for (int e = 0; e < 8; e++) q[e] = fmaxf(base[(size_t)e * HW + n], 0.f);

    float denom = ATT_EPS;
    #pragma unroll
    for (int e = 0; e < 8; e++) denom = fmaf(s[64 + e], q[e], denom);
    const float inv = 1.f / denom;

    const size_t obase = ((size_t)b * CCAT + head * 8) * HW + n;
    #pragma unroll
    for (int d = 0; d < 8; d++) {
        float o = 0.f;
        #pragma unroll
        for (int e = 0; e < 8; e++) o = fmaf(s[d * 8 + e], q[e], o);
        float val = o * inv;
        __nv_bfloat16 hh = __float2bfloat16_rn(val);
        g_attn_hi[obase + (size_t)d * HW] = hh;
        g_attn_lo[obase + (size_t)d * HW] =
            __float2bfloat16_rn(val - __bfloat162float(hh));
    }
}

// ==========================================================================
// launcher
// ==========================================================================
extern "C" void kernel_launch(void* const* d_in, const int* in_sizes, int n_in,
                              void* d_out, int out_size)
{
    const float* x            = (const float*)d_in[0];
    const float* qkv_w        = (const float*)d_in[1];
    const float* qkv_bn_scale = (const float*)d_in[2];
    const float* qkv_bn_bias  = (const float*)d_in[3];
    const float* agg_dw_w     = (const float*)d_in[4];
    const float* agg_dw_b     = (const float*)d_in[5];
    const float* agg_pw_w     = (const float*)d_in[6];
    const float* agg_pw_b     = (const float*)d_in[7];
    const float* proj_w       = (const float*)d_in[8];
    const float* proj_bn_scale= (const float*)d_in[9];
    const float* proj_bn_bias = (const float*)d_in[10];
    float* out = (float*)d_out;

    __nv_bfloat16 *xh, *xl, *wqh, *wql, *wph, *wpl, *ah, *al;
    cudaGetSymbolAddress((void**)&xh,  g_x_hi);
    cudaGetSymbolAddress((void**)&xl,  g_x_lo);
    cudaGetSymbolAddress((void**)&wqh, g_wqkv_hi);
    cudaGetSymbolAddress((void**)&wql, g_wqkv_lo);
    cudaGetSymbolAddress((void**)&wph, g_wproj_hi);
    cudaGetSymbolAddress((void**)&wpl, g_wproj_lo);
    cudaGetSymbolAddress((void**)&ah,  g_attn_hi);
    cudaGetSymbolAddress((void**)&al,  g_attn_lo);

    // 0) pre-split operands to bf16 hi/lo
    {
        int n4 = (BATCH * CIN * HW) / 4;
        to_hilo_kernel<<<(n4 + 255) / 256, 256>>>(
            (const float4*)x, (uint2*)xh, (uint2*)xl, n4);
        int w4 = (C3 * CIN) / 4;
        to_hilo_kernel<<<(w4 + 255) / 256, 256>>>(
            (const float4*)qkv_w, (uint2*)wqh, (uint2*)wql, w4);
        int p4 = (COUT * CCAT) / 4;
        to_hilo_kernel<<<(p4 + 255) / 256, 256>>>(
            (const float4*)proj_w, (uint2*)wph, (uint2*)wpl, p4);
    }
    // 1) qkv = relu(bn(conv1x1(x)))
    {
        float* gq;
        cudaGetSymbolAddress((void**)&gq, g_qkv);
        dim3 grid(HW / 128, C3 / 128, BATCH);
        gemm_bf16x3<C3, CIN><<<grid, 256>>>(
            wqh, wql, xh, xl, qkv_bn_scale, qkv_bn_bias, gq);
    }
    // 2) agg = pw(dw5x5(qkv))
    {
        dim3 grid(HW / 256, C3, BATCH);
        dw5x5_pw_kernel<<<grid, 256>>>(agg_dw_w, agg_dw_b, agg_pw_w, agg_pw_b);
    }
    // 3a) per-head vk / ksum
    {
        dim3 grid(NHEAD, BATCH);
        attn_reduce_kernel<<<grid, 256>>>();
    }
    // 3b) apply + normalize (emits bf16 hi/lo)
    {
        dim3 grid(HW / 256, NHEAD, BATCH);
        attn_apply_kernel<<<grid, 256>>>();
    }
    // 4) out = relu(bn(conv1x1(attn)))
    {
        dim3 grid(HW / 128, COUT / 128, BATCH);
        gemm_bf16x3<COUT, CCAT><<<grid, 256>>>(
            wph, wpl, ah, al, proj_bn_scale, proj_bn_bias, out);
    }
}

// round 8
// speedup vs baseline: 1.1927x; 1.0418x over previous
#include <cuda_runtime.h>
#include <cuda_bf16.h>
#include <mma.h>
#include <cstdint>

using namespace nvcuda;

// ---------------- problem constants ----------------
#define HW     4096      // 64*64
#define IMGW   64
#define BATCH  16
#define CIN    256
#define C3     768
#define CCAT   512
#define COUT   256
#define NHEAD  64
#define ATT_EPS 1e-5f

// ---------------- scratch (device globals; no allocations) ----------------
__device__ float g_qkv [(size_t)BATCH * C3   * HW];
__device__ float g_agg [(size_t)BATCH * C3   * HW];
__device__ float g_vk  [BATCH * NHEAD * 72];

// bf16 hi/lo operand mirrors (error-compensated GEMM inputs)
__device__ __nv_bfloat16 g_x_hi   [(size_t)BATCH * CIN  * HW];
__device__ __nv_bfloat16 g_x_lo   [(size_t)BATCH * CIN  * HW];
__device__ __nv_bfloat16 g_attn_hi[(size_t)BATCH * CCAT * HW];
__device__ __nv_bfloat16 g_attn_lo[(size_t)BATCH * CCAT * HW];
__device__ __nv_bfloat16 g_wqkv_hi[C3 * CIN];
__device__ __nv_bfloat16 g_wqkv_lo[C3 * CIN];
__device__ __nv_bfloat16 g_wproj_hi[COUT * CCAT];
__device__ __nv_bfloat16 g_wproj_lo[COUT * CCAT];

// ---------------- cp.async helpers ----------------
__device__ __forceinline__ void cp_async16(void* smem_dst, const void* gmem_src) {
    uint32_t s = (uint32_t)__cvta_generic_to_shared(smem_dst);
    asm volatile("cp.async.cg.shared.global [%0], [%1], 16;" :: "r"(s), "l"(gmem_src));
}
__device__ __forceinline__ void cp_commit() {
    asm volatile("cp.async.commit_group;");
}
template<int N>
__device__ __forceinline__ void cp_wait() {
    asm volatile("cp.async.wait_group %0;" :: "n"(N));
}

// ==========================================================================
// fp32 -> bf16 hi/lo conversion (one pass, float4 granularity)
// ==========================================================================
__global__ __launch_bounds__(256)
void to_hilo_kernel(const float4* __restrict__ src,
                    uint2* __restrict__ hi, uint2* __restrict__ lo, int n4)
{
    int i = blockIdx.x * 256 + threadIdx.x;
    if (i >= n4) return;
    float4 v = src[i];
    float xs[4] = {v.x, v.y, v.z, v.w};
    union { __nv_bfloat16 h[4]; uint2 u; } ph, pl;
    #pragma unroll
    for (int j = 0; j < 4; j++) {
        __nv_bfloat16 hh = __float2bfloat16_rn(xs[j]);
        ph.h[j] = hh;
        pl.h[j] = __float2bfloat16_rn(xs[j] - __bfloat162float(hh));
    }
    hi[i] = ph.u;
    lo[i] = pl.u;
}

// ==========================================================================
// bf16x3 wmma GEMM + BN + ReLU, cp.async 2-stage pipeline, 2 CTAs/SM.
//   Out[b,m,n] = relu(scale[m] * sum_k W[m,k] X[b,k,n] + bias[m])
// Block 128Mx128N, BK=32, 256 threads (8 warps, warp tile 64x32, 4x2 frags).
// ==========================================================================
#define LDA 40    // bf16 stride
#define LDB 136   // bf16 stride
#define LDC 132   // fp32 epilogue stride

#define OFF_AHI 0
#define OFF_ALO 10240
#define OFF_BHI 20480
#define OFF_BLO 29184
#define STAGE_BYTES 37888
#define SMEM_DYN (2 * STAGE_BYTES)   // 75776

template<int Mt, int Kt>
__global__ __launch_bounds__(256, 2)
void gemm_bf16x3(const __nv_bfloat16* __restrict__ Wh,
                 const __nv_bfloat16* __restrict__ Wl,
                 const __nv_bfloat16* __restrict__ Xh,
                 const __nv_bfloat16* __restrict__ Xl,
                 const float* __restrict__ scale,
                 const float* __restrict__ bias,
                 float* __restrict__ Out)
{
    extern __shared__ __align__(16) char dynsmem[];

    const int b     = blockIdx.z;
    const int mBase = blockIdx.y * 128;
    const int nBase = blockIdx.x * 128;
    const int tid   = threadIdx.x;
    const int wid   = tid >> 5;
    const int warpM = wid & 1;
    const int warpN = wid >> 1;

    const __nv_bfloat16* __restrict__ Xhb = Xh + (size_t)b * Kt * HW;
    const __nv_bfloat16* __restrict__ Xlb = Xl + (size_t)b * Kt * HW;

    // A staging: 512 uint4 (128 rows x 4 per row), 2 per thread
    const int aRow0 = (tid)       >> 2, aC0 = ((tid)       & 3) * 8;
    const int aRow1 = (tid + 256) >> 2, aC1 = ((tid + 256) & 3) * 8;
    // B staging: 512 uint4 (32 rows x 16 per row), 2 per thread
    const int bRow0 = (tid)       >> 4, bC0 = ((tid)       & 15) * 8;
    const int bRow1 = (tid + 256) >> 4, bC1 = ((tid + 256) & 15) * 8;

    auto stage_async = [&](int k0, char* buf) {
        __nv_bfloat16* Ahi = reinterpret_cast<__nv_bfloat16*>(buf + OFF_AHI);
        __nv_bfloat16* Alo = reinterpret_cast<__nv_bfloat16*>(buf + OFF_ALO);
        __nv_bfloat16* Bhi = reinterpret_cast<__nv_bfloat16*>(buf + OFF_BHI);
        __nv_bfloat16* Blo = reinterpret_cast<__nv_bfloat16*>(buf + OFF_BLO);
        cp_async16(&Ahi[aRow0 * LDA + aC0], &Wh[(size_t)(mBase + aRow0) * Kt + k0 + aC0]);
        cp_async16(&Ahi[aRow1 * LDA + aC1], &Wh[(size_t)(mBase + aRow1) * Kt + k0 + aC1]);
        cp_async16(&Alo[aRow0 * LDA + aC0], &Wl[(size_t)(mBase + aRow0) * Kt + k0 + aC0]);
        cp_async16(&Alo[aRow1 * LDA + aC1], &Wl[(size_t)(mBase + aRow1) * Kt + k0 + aC1]);
        cp_async16(&Bhi[bRow0 * LDB + bC0], &Xhb[(size_t)(k0 + bRow0) * HW + nBase + bC0]);
        cp_async16(&Bhi[bRow1 * LDB + bC1], &Xhb[(size_t)(k0 + bRow1) * HW + nBase + bC1]);
        cp_async16(&Blo[bRow0 * LDB + bC0], &Xlb[(size_t)(k0 + bRow0) * HW + nBase + bC0]);
        cp_async16(&Blo[bRow1 * LDB + bC1], &Xlb[(size_t)(k0 + bRow1) * HW + nBase + bC1]);
    };

    wmma::fragment<wmma::accumulator, 16, 16, 16, float> acc[4][2];
    #pragma unroll
    for (int i = 0; i < 4; i++)
        #pragma unroll
        for (int j = 0; j < 2; j++) wmma::fill_fragment(acc[i][j], 0.f);

    constexpr int NCHUNK = Kt / 32;
    stage_async(0, dynsmem);
    cp_commit();

    #pragma unroll 1
    for (int chunk = 0; chunk < NCHUNK; chunk++) {
        if (chunk + 1 < NCHUNK) {
            stage_async((chunk + 1) * 32, dynsmem + ((chunk + 1) & 1) * STAGE_BYTES);
            cp_commit();
            cp_wait<1>();
        } else {
            cp_wait<0>();
        }
        __syncthreads();

        char* buf = dynsmem + (chunk & 1) * STAGE_BYTES;
        __nv_bfloat16* Ahi = reinterpret_cast<__nv_bfloat16*>(buf + OFF_AHI);
        __nv_bfloat16* Alo = reinterpret_cast<__nv_bfloat16*>(buf + OFF_ALO);
        __nv_bfloat16* Bhi = reinterpret_cast<__nv_bfloat16*>(buf + OFF_BHI);
        __nv_bfloat16* Blo = reinterpret_cast<__nv_bfloat16*>(buf + OFF_BLO);

        #pragma unroll
        for (int kk = 0; kk < 2; kk++) {
            wmma::fragment<wmma::matrix_b, 16, 16, 16, __nv_bfloat16,
                           wmma::row_major> bfh[2], bfl[2];
            #pragma unroll
            for (int j = 0; j < 2; j++) {
                const int ro = (kk * 16) * LDB + warpN * 32 + j * 16;
                wmma::load_matrix_sync(bfh[j], &Bhi[ro], LDB);
                wmma::load_matrix_sync(bfl[j], &Blo[ro], LDB);
            }
            #pragma unroll
            for (int i = 0; i < 4; i++) {
                wmma::fragment<wmma::matrix_a, 16, 16, 16, __nv_bfloat16,
                               wmma::row_major> afh, afl;
                const int ro = (warpM * 64 + i * 16) * LDA + kk * 16;
                wmma::load_matrix_sync(afh, &Ahi[ro], LDA);
                wmma::load_matrix_sync(afl, &Alo[ro], LDA);
                #pragma unroll
                for (int j = 0; j < 2; j++) {
                    wmma::mma_sync(acc[i][j], afl, bfh[j], acc[i][j]);
                    wmma::mma_sync(acc[i][j], afh, bfl[j], acc[i][j]);
                    wmma::mma_sync(acc[i][j], afh, bfh[j], acc[i][j]);
                }
            }
        }
        __syncthreads();
    }

    // ---- epilogue: two 64-row passes via smem (stage 0 reuse), BN + ReLU
    float* Cs = reinterpret_cast<float*>(dynsmem);
    #pragma unroll
    for (int p = 0; p < 2; p++) {
        if (warpM == p) {
            #pragma unroll
            for (int i = 0; i < 4; i++)
                #pragma unroll
                for (int j = 0; j < 2; j++)
                    wmma::store_matrix_sync(
                        &Cs[(i * 16) * LDC + warpN * 32 + j * 16],
                        acc[i][j], LDC, wmma::mem_row_major);
        }
        __syncthreads();
        #pragma unroll
        for (int t = 0; t < 8; t++) {
            int idx = tid + t * 256;
            int r = idx >> 5, c4 = (idx & 31) * 4;
            int m = mBase + p * 64 + r;
            const float sc = scale[m], bi = bias[m];
            float4 v = *reinterpret_cast<const float4*>(&Cs[r * LDC + c4]);
            v.x = fmaxf(fmaf(v.x, sc, bi), 0.f);
            v.y = fmaxf(fmaf(v.y, sc, bi), 0.f);
            v.z = fmaxf(fmaf(v.z, sc, bi), 0.f);
            v.w = fmaxf(fmaf(v.w, sc, bi), 0.f);
            *reinterpret_cast<float4*>(
                &Out[(size_t)b * Mt * HW + (size_t)m * HW + nBase + c4]) = v;
        }
        __syncthreads();
    }
}

// ==========================================================================
// Fused depthwise 5x5 (pad 2, +bias) then per-channel 1x1 (*w, +bias).
// ==========================================================================
__global__ __launch_bounds__(256)
void dw5x5_pw_kernel(const float* __restrict__ dw_w,
                     const float* __restrict__ dw_b,
                     const float* __restrict__ pw_w,
                     const float* __restrict__ pw_b)
{
    const int c = blockIdx.y;
    const int b = blockIdx.z;
    const int p = blockIdx.x * 256 + threadIdx.x;
    const int y = p >> 6;
    const int x = p & 63;

    const float* __restrict__ src = g_qkv + ((size_t)b * C3 + c) * HW;

    float wreg[25];
    #pragma unroll
    for (int i = 0; i < 25; i++) wreg[i] = __ldg(&dw_w[c * 25 + i]);

    float s = 0.f;
    #pragma unroll
    for (int dy = 0; dy < 5; dy++) {
        const int yy = y + dy - 2;
        if (yy < 0 || yy >= IMGW) continue;
        const float* row = src + yy * IMGW;
        #pragma unroll
        for (int dx = 0; dx < 5; dx++) {
            const int xx = x + dx - 2;
            if (xx < 0 || xx >= IMGW) continue;
            s = fmaf(__ldg(&row[xx]), wreg[dy * 5 + dx], s);
        }
    }
    s = fmaf(s + __ldg(&dw_b[c]), __ldg(&pw_w[c]), __ldg(&pw_b[c]));
    g_agg[((size_t)b * C3 + c) * HW + p] = s;
}

// ==========================================================================
// Attention phase 1: per (b, head): vk[d][e] = sum_n v*relu(k); ksum[e]
// ==========================================================================
__global__ __launch_bounds__(256)
void attn_reduce_kernel()
{
    const int head = blockIdx.x;
    const int b    = blockIdx.y;
    const float* __restrict__ src = (head < 32) ? g_qkv : g_agg;
    const int ch0 = (head & 31) * 24;
    const float* __restrict__ base = src + ((size_t)b * C3 + ch0) * HW;

    float acc[72];
    #pragma unroll
    for (int i = 0; i < 72; i++) acc[i] = 0.f;

    for (int n = threadIdx.x; n < HW; n += 256) {
        float kv[8], vv[8];
        #pragma unroll
        for (int e = 0; e < 8; e++) kv[e] = fmaxf(base[(size_t)(8 + e) * HW + n], 0.f);
        #pragma unroll
        for (int d = 0; d < 8; d++) vv[d] = base[(size_t)(16 + d) * HW + n];
        #pragma unroll
        for (int d = 0; d < 8; d++)
            #pragma unroll
            for (int e = 0; e < 8; e++)
                acc[d * 8 + e] = fmaf(vv[d], kv[e], acc[d * 8 + e]);
        #pragma unroll
        for (int e = 0; e < 8; e++) acc[64 + e] += kv[e];
    }

    __shared__ float s_acc[72];
    if (threadIdx.x < 72) s_acc[threadIdx.x] = 0.f;
    __syncthreads();

    const int lane = threadIdx.x & 31;
    #pragma unroll
    for (int i = 0; i < 72; i++) {
        float v = acc[i];
        #pragma unroll
        for (int off = 16; off > 0; off >>= 1)
            v += __shfl_down_sync(0xffffffffu, v, off);
        if (lane == 0) atomicAdd(&s_acc[i], v);
    }
    __syncthreads();
    if (threadIdx.x < 72)
        g_vk[((size_t)b * NHEAD + head) * 72 + threadIdx.x] = s_acc[threadIdx.x];
}

// ==========================================================================
// Attention phase 2: apply + normalize; emits bf16 hi/lo for the proj GEMM
// ==========================================================================
__global__ __launch_bounds__(256)
void attn_apply_kernel()
{
    const int head = blockIdx.y;
    const int b    = blockIdx.z;
    const int n    = blockIdx.x * 256 + threadIdx.x;

    __shared__ float s[72];
    if (threadIdx.x < 72)
        s[threadIdx.x] = g_vk[((size_t)b * NHEAD + head) * 72 + threadIdx.x];
    __syncthreads();

    const float* __restrict__ src = (head < 32) ? g_qkv : g_agg;
    const int ch0 = (head & 31) * 24;
    const float* __restrict__ base = src + ((size_t)b * C3 + ch0) * HW;

    float q[8];
    #pragma unroll
    for (int e = 0; e < 8; e++) q[e] = fmaxf(base[(size_t)e * HW + n], 0.f);

    float denom = ATT_EPS;
    #pragma unroll
    for (int e = 0; e < 8; e++) denom = fmaf(s[64 + e], q[e], denom);
    const float inv = 1.f / denom;

    const size_t obase = ((size_t)b * CCAT + head * 8) * HW + n;
    #pragma unroll
    for (int d = 0; d < 8; d++) {
        float o = 0.f;
        #pragma unroll
        for (int e = 0; e < 8; e++) o = fmaf(s[d * 8 + e], q[e], o);
        float val = o * inv;
        __nv_bfloat16 hh = __float2bfloat16_rn(val);
        g_attn_hi[obase + (size_t)d * HW] = hh;
        g_attn_lo[obase + (size_t)d * HW] =
            __float2bfloat16_rn(val - __bfloat162float(hh));
    }
}

// ==========================================================================
// launcher
// ==========================================================================
extern "C" void kernel_launch(void* const* d_in, const int* in_sizes, int n_in,
                              void* d_out, int out_size)
{
    const float* x            = (const float*)d_in[0];
    const float* qkv_w        = (const float*)d_in[1];
    const float* qkv_bn_scale = (const float*)d_in[2];
    const float* qkv_bn_bias  = (const float*)d_in[3];
    const float* agg_dw_w     = (const float*)d_in[4];
    const float* agg_dw_b     = (const float*)d_in[5];
    const float* agg_pw_w     = (const float*)d_in[6];
    const float* agg_pw_b     = (const float*)d_in[7];
    const float* proj_w       = (const float*)d_in[8];
    const float* proj_bn_scale= (const float*)d_in[9];
    const float* proj_bn_bias = (const float*)d_in[10];
    float* out = (float*)d_out;

    __nv_bfloat16 *xh, *xl, *wqh, *wql, *wph, *wpl, *ah, *al;
    cudaGetSymbolAddress((void**)&xh,  g_x_hi);
    cudaGetSymbolAddress((void**)&xl,  g_x_lo);
    cudaGetSymbolAddress((void**)&wqh, g_wqkv_hi);
    cudaGetSymbolAddress((void**)&wql, g_wqkv_lo);
    cudaGetSymbolAddress((void**)&wph, g_wproj_hi);
    cudaGetSymbolAddress((void**)&wpl, g_wproj_lo);
    cudaGetSymbolAddress((void**)&ah,  g_attn_hi);
    cudaGetSymbolAddress((void**)&al,  g_attn_lo);

    (void)cudaFuncSetAttribute(gemm_bf16x3<C3, CIN>,
                               cudaFuncAttributeMaxDynamicSharedMemorySize, SMEM_DYN);
    (void)cudaFuncSetAttribute(gemm_bf16x3<COUT, CCAT>,
                               cudaFuncAttributeMaxDynamicSharedMemorySize, SMEM_DYN);

    // 0) pre-split operands to bf16 hi/lo
    {
        int n4 = (BATCH * CIN * HW) / 4;
        to_hilo_kernel<<<(n4 + 255) / 256, 256>>>(
            (const float4*)x, (uint2*)xh, (uint2*)xl, n4);
        int w4 = (C3 * CIN) / 4;
        to_hilo_kernel<<<(w4 + 255) / 256, 256>>>(
            (const float4*)qkv_w, (uint2*)wqh, (uint2*)wql, w4);
        int p4 = (COUT * CCAT) / 4;
        to_hilo_kernel<<<(p4 + 255) / 256, 256>>>(
            (const float4*)proj_w, (uint2*)wph, (uint2*)wpl, p4);
    }
    // 1) qkv = relu(bn(conv1x1(x)))
    {
        float* gq;
        cudaGetSymbolAddress((void**)&gq, g_qkv);
        dim3 grid(HW / 128, C3 / 128, BATCH);
        gemm_bf16x3<C3, CIN><<<grid, 256, SMEM_DYN>>>(
            wqh, wql, xh, xl, qkv_bn_scale, qkv_bn_bias, gq);
    }
    // 2) agg = pw(dw5x5(qkv))
    {
        dim3 grid(HW / 256, C3, BATCH);
        dw5x5_pw_kernel<<<grid, 256>>>(agg_dw_w, agg_dw_b, agg_pw_w, agg_pw_b);
    }
    // 3a) per-head vk / ksum
    {
        dim3 grid(NHEAD, BATCH);
        attn_reduce_kernel<<<grid, 256>>>();
    }
    // 3b) apply + normalize (emits bf16 hi/lo)
    {
        dim3 grid(HW / 256, NHEAD, BATCH);
        attn_apply_kernel<<<grid, 256>>>();
    }
    // 4) out = relu(bn(conv1x1(attn)))
    {
        dim3 grid(HW / 128, COUT / 128, BATCH);
        gemm_bf16x3<COUT, CCAT><<<grid, 256, SMEM_DYN>>>(
            wph, wpl, ah, al, proj_bn_scale, proj_bn_bias, out);
    }
}

// round 9
// speedup vs baseline: 1.3949x; 1.1696x over previous
#include <cuda_runtime.h>
#include <cuda_bf16.h>
#include <mma.h>
#include <cstdint>

using namespace nvcuda;

// ---------------- problem constants ----------------
#define HW     4096      // 64*64
#define IMGW   64
#define BATCH  16
#define CIN    256
#define C3     768
#define CCAT   512
#define COUT   256
#define NHEAD  64
#define ATT_EPS 1e-5f

// ---------------- scratch (device globals; no allocations) ----------------
__device__ float g_qkv [(size_t)BATCH * C3   * HW];
__device__ float g_agg [(size_t)BATCH * C3   * HW];
__device__ float g_vk  [BATCH * NHEAD * 72];

// bf16 hi/lo operand mirrors (error-compensated GEMM inputs)
__device__ __nv_bfloat16 g_x_hi   [(size_t)BATCH * CIN  * HW];
__device__ __nv_bfloat16 g_x_lo   [(size_t)BATCH * CIN  * HW];
__device__ __nv_bfloat16 g_attn_hi[(size_t)BATCH * CCAT * HW];
__device__ __nv_bfloat16 g_attn_lo[(size_t)BATCH * CCAT * HW];
__device__ __nv_bfloat16 g_wqkv_hi[C3 * CIN];
__device__ __nv_bfloat16 g_wqkv_lo[C3 * CIN];
__device__ __nv_bfloat16 g_wproj_hi[COUT * CCAT];
__device__ __nv_bfloat16 g_wproj_lo[COUT * CCAT];

// ---------------- cp.async helpers ----------------
__device__ __forceinline__ void cp_async16(void* smem_dst, const void* gmem_src) {
    uint32_t s = (uint32_t)__cvta_generic_to_shared(smem_dst);
    asm volatile("cp.async.cg.shared.global [%0], [%1], 16;" :: "r"(s), "l"(gmem_src));
}
__device__ __forceinline__ void cp_commit() {
    asm volatile("cp.async.commit_group;");
}
template<int N>
__device__ __forceinline__ void cp_wait() {
    asm volatile("cp.async.wait_group %0;" :: "n"(N));
}

// ==========================================================================
// fp32 -> bf16 hi/lo conversion (one pass, float4 granularity)
// ==========================================================================
__global__ __launch_bounds__(256)
void to_hilo_kernel(const float4* __restrict__ src,
                    uint2* __restrict__ hi, uint2* __restrict__ lo, int n4)
{
    int i = blockIdx.x * 256 + threadIdx.x;
    if (i >= n4) return;
    float4 v = src[i];
    float xs[4] = {v.x, v.y, v.z, v.w};
    union { __nv_bfloat16 h[4]; uint2 u; } ph, pl;
    #pragma unroll
    for (int j = 0; j < 4; j++) {
        __nv_bfloat16 hh = __float2bfloat16_rn(xs[j]);
        ph.h[j] = hh;
        pl.h[j] = __float2bfloat16_rn(xs[j] - __bfloat162float(hh));
    }
    hi[i] = ph.u;
    lo[i] = pl.u;
}

// ==========================================================================
// bf16x3 wmma GEMM + BN + ReLU, cp.async 3-stage pipeline, 2 CTAs/SM.
//   Out[b,m,n] = relu(scale[m] * sum_k W[m,k] X[b,k,n] + bias[m])
// Block 128Mx128N, BK=32, 256 threads (8 warps, warp tile 64x32, 4x2 frags).
// One __syncthreads per chunk; single-pass epilogue.
// ==========================================================================
#define LDA 40    // bf16 stride
#define LDB 136   // bf16 stride
#define LDC 132   // fp32 epilogue stride

#define OFF_AHI 0
#define OFF_ALO 10240
#define OFF_BHI 20480
#define OFF_BLO 29184
#define STAGE_BYTES 37888
#define NSTAGE 3
#define SMEM_DYN (NSTAGE * STAGE_BYTES)   // 113664

template<int Mt, int Kt>
__global__ __launch_bounds__(256, 2)
void gemm_bf16x3(const __nv_bfloat16* __restrict__ Wh,
                 const __nv_bfloat16* __restrict__ Wl,
                 const __nv_bfloat16* __restrict__ Xh,
                 const __nv_bfloat16* __restrict__ Xl,
                 const float* __restrict__ scale,
                 const float* __restrict__ bias,
                 float* __restrict__ Out)
{
    extern __shared__ __align__(16) char dynsmem[];

    const int b     = blockIdx.z;
    const int mBase = blockIdx.y * 128;
    const int nBase = blockIdx.x * 128;
    const int tid   = threadIdx.x;
    const int wid   = tid >> 5;
    const int warpM = wid & 1;
    const int warpN = wid >> 1;

    const __nv_bfloat16* __restrict__ Xhb = Xh + (size_t)b * Kt * HW;
    const __nv_bfloat16* __restrict__ Xlb = Xl + (size_t)b * Kt * HW;

    // A staging: 512 uint4 (128 rows x 4 per row), 2 per thread
    const int aRow0 = (tid)       >> 2, aC0 = ((tid)       & 3) * 8;
    const int aRow1 = (tid + 256) >> 2, aC1 = ((tid + 256) & 3) * 8;
    // B staging: 512 uint4 (32 rows x 16 per row), 2 per thread
    const int bRow0 = (tid)       >> 4, bC0 = ((tid)       & 15) * 8;
    const int bRow1 = (tid + 256) >> 4, bC1 = ((tid + 256) & 15) * 8;

    auto stage_async = [&](int k0, char* buf) {
        __nv_bfloat16* Ahi = reinterpret_cast<__nv_bfloat16*>(buf + OFF_AHI);
        __nv_bfloat16* Alo = reinterpret_cast<__nv_bfloat16*>(buf + OFF_ALO);
        __nv_bfloat16* Bhi = reinterpret_cast<__nv_bfloat16*>(buf + OFF_BHI);
        __nv_bfloat16* Blo = reinterpret_cast<__nv_bfloat16*>(buf + OFF_BLO);
        cp_async16(&Ahi[aRow0 * LDA + aC0], &Wh[(size_t)(mBase + aRow0) * Kt + k0 + aC0]);
        cp_async16(&Ahi[aRow1 * LDA + aC1], &Wh[(size_t)(mBase + aRow1) * Kt + k0 + aC1]);
        cp_async16(&Alo[aRow0 * LDA + aC0], &Wl[(size_t)(mBase + aRow0) * Kt + k0 + aC0]);
        cp_async16(&Alo[aRow1 * LDA + aC1], &Wl[(size_t)(mBase + aRow1) * Kt + k0 + aC1]);
        cp_async16(&Bhi[bRow0 * LDB + bC0], &Xhb[(size_t)(k0 + bRow0) * HW + nBase + bC0]);
        cp_async16(&Bhi[bRow1 * LDB + bC1], &Xhb[(size_t)(k0 + bRow1) * HW + nBase + bC1]);
        cp_async16(&Blo[bRow0 * LDB + bC0], &Xlb[(size_t)(k0 + bRow0) * HW + nBase + bC0]);
        cp_async16(&Blo[bRow1 * LDB + bC1], &Xlb[(size_t)(k0 + bRow1) * HW + nBase + bC1]);
    };

    wmma::fragment<wmma::accumulator, 16, 16, 16, float> acc[4][2];
    #pragma unroll
    for (int i = 0; i < 4; i++)
        #pragma unroll
        for (int j = 0; j < 2; j++) wmma::fill_fragment(acc[i][j], 0.f);

    constexpr int NCHUNK = Kt / 32;
    // prologue: stage chunks 0 and 1
    stage_async(0, dynsmem);
    cp_commit();
    stage_async(32, dynsmem + STAGE_BYTES);
    cp_commit();

    #pragma unroll 1
    for (int chunk = 0; chunk < NCHUNK; chunk++) {
        if (chunk < NCHUNK - 1) cp_wait<1>(); else cp_wait<0>();
        __syncthreads();   // chunk's data visible + prev compute done (buffer reuse safe)
        if (chunk + 2 < NCHUNK) {
            stage_async((chunk + 2) * 32, dynsmem + ((chunk + 2) % NSTAGE) * STAGE_BYTES);
            cp_commit();
        }

        char* buf = dynsmem + (chunk % NSTAGE) * STAGE_BYTES;
        __nv_bfloat16* Ahi = reinterpret_cast<__nv_bfloat16*>(buf + OFF_AHI);
        __nv_bfloat16* Alo = reinterpret_cast<__nv_bfloat16*>(buf + OFF_ALO);
        __nv_bfloat16* Bhi = reinterpret_cast<__nv_bfloat16*>(buf + OFF_BHI);
        __nv_bfloat16* Blo = reinterpret_cast<__nv_bfloat16*>(buf + OFF_BLO);

        #pragma unroll
        for (int kk = 0; kk < 2; kk++) {
            wmma::fragment<wmma::matrix_b, 16, 16, 16, __nv_bfloat16,
                           wmma::row_major> bfh[2], bfl[2];
            #pragma unroll
            for (int j = 0; j < 2; j++) {
                const int ro = (kk * 16) * LDB + warpN * 32 + j * 16;
                wmma::load_matrix_sync(bfh[j], &Bhi[ro], LDB);
                wmma::load_matrix_sync(bfl[j], &Blo[ro], LDB);
            }
            #pragma unroll
            for (int i = 0; i < 4; i++) {
                wmma::fragment<wmma::matrix_a, 16, 16, 16, __nv_bfloat16,
                               wmma::row_major> afh, afl;
                const int ro = (warpM * 64 + i * 16) * LDA + kk * 16;
                wmma::load_matrix_sync(afh, &Ahi[ro], LDA);
                wmma::load_matrix_sync(afl, &Alo[ro], LDA);
                #pragma unroll
                for (int j = 0; j < 2; j++) {
                    wmma::mma_sync(acc[i][j], afl, bfh[j], acc[i][j]);
                    wmma::mma_sync(acc[i][j], afh, bfl[j], acc[i][j]);
                    wmma::mma_sync(acc[i][j], afh, bfh[j], acc[i][j]);
                }
            }
        }
    }

    // ---- single-pass epilogue: Cs[128][LDC] = 67.6KB fits the stage area
    __syncthreads();
    float* Cs = reinterpret_cast<float*>(dynsmem);
    #pragma unroll
    for (int i = 0; i < 4; i++)
        #pragma unroll
        for (int j = 0; j < 2; j++)
            wmma::store_matrix_sync(
                &Cs[(warpM * 64 + i * 16) * LDC + warpN * 32 + j * 16],
                acc[i][j], LDC, wmma::mem_row_major);
    __syncthreads();
    #pragma unroll
    for (int t = 0; t < 16; t++) {
        int idx = tid + t * 256;          // 4096 float4
        int r = idx >> 5, c4 = (idx & 31) * 4;
        int m = mBase + r;
        const float sc = scale[m], bi = bias[m];
        float4 v = *reinterpret_cast<const float4*>(&Cs[r * LDC + c4]);
        v.x = fmaxf(fmaf(v.x, sc, bi), 0.f);
        v.y = fmaxf(fmaf(v.y, sc, bi), 0.f);
        v.z = fmaxf(fmaf(v.z, sc, bi), 0.f);
        v.w = fmaxf(fmaf(v.w, sc, bi), 0.f);
        *reinterpret_cast<float4*>(
            &Out[(size_t)b * Mt * HW + (size_t)m * HW + nBase + c4]) = v;
    }
}

// ==========================================================================
// Fused depthwise 5x5 (pad 2, +bias) then per-channel 1x1 (*w, +bias),
// smem-tiled: one block per (b,c), 68x68 halo tile staged once.
// ==========================================================================
#define TILE_W 68
__global__ __launch_bounds__(256)
void dw5x5_pw_kernel(const float* __restrict__ dw_w,
                     const float* __restrict__ dw_b,
                     const float* __restrict__ pw_w,
                     const float* __restrict__ pw_b)
{
    __shared__ float tile[TILE_W * TILE_W];
    const int c = blockIdx.x;
    const int b = blockIdx.y;
    const int tid = threadIdx.x;

    const float* __restrict__ src = g_qkv + ((size_t)b * C3 + c) * HW;

    // stage 68x68 halo tile (zero padding outside)
    for (int idx = tid; idx < TILE_W * TILE_W; idx += 256) {
        int r = idx / TILE_W - 2;
        int cc = idx % TILE_W - 2;
        float v = 0.f;
        if ((unsigned)r < IMGW && (unsigned)cc < IMGW) v = src[r * IMGW + cc];
        tile[idx] = v;
    }

    float wreg[25];
    #pragma unroll
    for (int i = 0; i < 25; i++) wreg[i] = __ldg(&dw_w[c * 25 + i]);
    const float dwb = __ldg(&dw_b[c]);
    const float pww = __ldg(&pw_w[c]);
    const float pwb = __ldg(&pw_b[c]);
    __syncthreads();

    float* dst = g_agg + ((size_t)b * C3 + c) * HW;
    #pragma unroll
    for (int t = 0; t < 16; t++) {
        int p = tid + t * 256;
        int y = p >> 6, x = p & 63;
        float s = 0.f;
        #pragma unroll
        for (int dy = 0; dy < 5; dy++) {
            const float* trow = &tile[(y + dy) * TILE_W + x];
            #pragma unroll
            for (int dx = 0; dx < 5; dx++)
                s = fmaf(trow[dx], wreg[dy * 5 + dx], s);
        }
        dst[p] = fmaf(s + dwb, pww, pwb);
    }
}

// ==========================================================================
// Attention phase 1: per (b, head): vk[d][e] = sum_n v*relu(k); ksum[e]
// ==========================================================================
__global__ __launch_bounds__(256)
void attn_reduce_kernel()
{
    const int head = blockIdx.x;
    const int b    = blockIdx.y;
    const float* __restrict__ src = (head < 32) ? g_qkv : g_agg;
    const int ch0 = (head & 31) * 24;
    const float* __restrict__ base = src + ((size_t)b * C3 + ch0) * HW;

    float acc[72];
    #pragma unroll
    for (int i = 0; i < 72; i++) acc[i] = 0.f;

    for (int n = threadIdx.x; n < HW; n += 256) {
        float kv[8], vv[8];
        #pragma unroll
        for (int e = 0; e < 8; e++) kv[e] = fmaxf(base[(size_t)(8 + e) * HW + n], 0.f);
        #pragma unroll
        for (int d = 0; d < 8; d++) vv[d] = base[(size_t)(16 + d) * HW + n];
        #pragma unroll
        for (int d = 0; d < 8; d++)
            #pragma unroll
            for (int e = 0; e < 8; e++)
                acc[d * 8 + e] = fmaf(vv[d], kv[e], acc[d * 8 + e]);
        #pragma unroll
        for (int e = 0; e < 8; e++) acc[64 + e] += kv[e];
    }

    __shared__ float s_acc[72];
    if (threadIdx.x < 72) s_acc[threadIdx.x] = 0.f;
    __syncthreads();

    const int lane = threadIdx.x & 31;
    #pragma unroll
    for (int i = 0; i < 72; i++) {
        float v = acc[i];
        #pragma unroll
        for (int off = 16; off > 0; off >>= 1)
            v += __shfl_down_sync(0xffffffffu, v, off);
        if (lane == 0) atomicAdd(&s_acc[i], v);
    }
    __syncthreads();
    if (threadIdx.x < 72)
        g_vk[((size_t)b * NHEAD + head) * 72 + threadIdx.x] = s_acc[threadIdx.x];
}

// ==========================================================================
// Attention phase 2: apply + normalize; emits bf16 hi/lo for the proj GEMM
// ==========================================================================
__global__ __launch_bounds__(256)
void attn_apply_kernel()
{
    const int head = blockIdx.y;
    const int b    = blockIdx.z;
    const int n    = blockIdx.x * 256 + threadIdx.x;

    __shared__ float s[72];
    if (threadIdx.x < 72)
        s[threadIdx.x] = g_vk[((size_t)b * NHEAD + head) * 72 + threadIdx.x];
    __syncthreads();

    const float* __restrict__ src = (head < 32) ? g_qkv : g_agg;
    const int ch0 = (head & 31) * 24;
    const float* __restrict__ base = src + ((size_t)b * C3 + ch0) * HW;

    float q[8];
    #pragma unroll
    for (int e = 0; e < 8; e++) q[e] = fmaxf(base[(size_t)e * HW + n], 0.f);

    float denom = ATT_EPS;
    #pragma unroll
    for (int e = 0; e < 8; e++) denom = fmaf(s[64 + e], q[e], denom);
    const float inv = 1.f / denom;

    const size_t obase = ((size_t)b * CCAT + head * 8) * HW + n;
    #pragma unroll
    for (int d = 0; d < 8; d++) {
        float o = 0.f;
        #pragma unroll
        for (int e = 0; e < 8; e++) o = fmaf(s[d * 8 + e], q[e], o);
        float val = o * inv;
        __nv_bfloat16 hh = __float2bfloat16_rn(val);
        g_attn_hi[obase + (size_t)d * HW] = hh;
        g_attn_lo[obase + (size_t)d * HW] =
            __float2bfloat16_rn(val - __bfloat162float(hh));
    }
}

// ==========================================================================
// launcher
// ==========================================================================
extern "C" void kernel_launch(void* const* d_in, const int* in_sizes, int n_in,
                              void* d_out, int out_size)
{
    const float* x            = (const float*)d_in[0];
    const float* qkv_w        = (const float*)d_in[1];
    const float* qkv_bn_scale = (const float*)d_in[2];
    const float* qkv_bn_bias  = (const float*)d_in[3];
    const float* agg_dw_w     = (const float*)d_in[4];
    const float* agg_dw_b     = (const float*)d_in[5];
    const float* agg_pw_w     = (const float*)d_in[6];
    const float* agg_pw_b     = (const float*)d_in[7];
    const float* proj_w       = (const float*)d_in[8];
    const float* proj_bn_scale= (const float*)d_in[9];
    const float* proj_bn_bias = (const float*)d_in[10];
    float* out = (float*)d_out;

    __nv_bfloat16 *xh, *xl, *wqh, *wql, *wph, *wpl, *ah, *al;
    cudaGetSymbolAddress((void**)&xh,  g_x_hi);
    cudaGetSymbolAddress((void**)&xl,  g_x_lo);
    cudaGetSymbolAddress((void**)&wqh, g_wqkv_hi);
    cudaGetSymbolAddress((void**)&wql, g_wqkv_lo);
    cudaGetSymbolAddress((void**)&wph, g_wproj_hi);
    cudaGetSymbolAddress((void**)&wpl, g_wproj_lo);
    cudaGetSymbolAddress((void**)&ah,  g_attn_hi);
    cudaGetSymbolAddress((void**)&al,  g_attn_lo);

    (void)cudaFuncSetAttribute(gemm_bf16x3<C3, CIN>,
                               cudaFuncAttributeMaxDynamicSharedMemorySize, SMEM_DYN);
    (void)cudaFuncSetAttribute(gemm_bf16x3<COUT, CCAT>,
                               cudaFuncAttributeMaxDynamicSharedMemorySize, SMEM_DYN);

    // 0) pre-split operands to bf16 hi/lo
    {
        int n4 = (BATCH * CIN * HW) / 4;
        to_hilo_kernel<<<(n4 + 255) / 256, 256>>>(
            (const float4*)x, (uint2*)xh, (uint2*)xl, n4);
        int w4 = (C3 * CIN) / 4;
        to_hilo_kernel<<<(w4 + 255) / 256, 256>>>(
            (const float4*)qkv_w, (uint2*)wqh, (uint2*)wql, w4);
        int p4 = (COUT * CCAT) / 4;
        to_hilo_kernel<<<(p4 + 255) / 256, 256>>>(
            (const float4*)proj_w, (uint2*)wph, (uint2*)wpl, p4);
    }
    // 1) qkv = relu(bn(conv1x1(x)))
    {
        float* gq;
        cudaGetSymbolAddress((void**)&gq, g_qkv);
        dim3 grid(HW / 128, C3 / 128, BATCH);
        gemm_bf16x3<C3, CIN><<<grid, 256, SMEM_DYN>>>(
            wqh, wql, xh, xl, qkv_bn_scale, qkv_bn_bias, gq);
    }
    // 2) agg = pw(dw5x5(qkv))
    {
        dim3 grid(C3, BATCH);
        dw5x5_pw_kernel<<<grid, 256>>>(agg_dw_w, agg_dw_b, agg_pw_w, agg_pw_b);
    }
    // 3a) per-head vk / ksum
    {
        dim3 grid(NHEAD, BATCH);
        attn_reduce_kernel<<<grid, 256>>>();
    }
    // 3b) apply + normalize (emits bf16 hi/lo)
    {
        dim3 grid(HW / 256, NHEAD, BATCH);
        attn_apply_kernel<<<grid, 256>>>();
    }
    // 4) out = relu(bn(conv1x1(attn)))
    {
        dim3 grid(HW / 128, COUT / 128, BATCH);
        gemm_bf16x3<COUT, CCAT><<<grid, 256, SMEM_DYN>>>(
            wph, wpl, ah, al, proj_bn_scale, proj_bn_bias, out);
    }
}